// round 3
// baseline (speedup 1.0000x reference)
#include <cuda_runtime.h>

#define NN 50000
#define NE 800000
#define HD 64
#define NL 4
#define AS_LD 68   // padded leading dim for K-major A/H tiles (68*4B = 272B, 16B-aligned rows)

// ---------------- scratch (device globals: allocation-free rule) ----------------
__device__ __align__(16) float g_h[2][(size_t)NN * HD];      // ping-pong node features
__device__ __align__(16) float g_agg[(size_t)NN * HD];       // per-layer aggregation
__device__ __align__(16) int   g_src[NE];
__device__ __align__(16) int   g_dst[NE];
__device__ __align__(16) float g_evec[(size_t)NE * 3];
__device__ __align__(16) float g_w1eff[NL][132 * 64];        // fused edge-W1
__device__ __align__(16) float g_b1eff[NL][64];

// ---------------- f32x2 packed-FMA helpers (Blackwell FFMA2) ----------------
__device__ __forceinline__ void ffma2(unsigned long long& d, unsigned long long a, unsigned long long b) {
    asm("fma.rn.f32x2 %0, %1, %2, %0;" : "+l"(d) : "l"(a), "l"(b));
}
__device__ __forceinline__ unsigned long long splat2(float x) {
    unsigned long long r; asm("mov.b64 %0, {%1, %1};" : "=l"(r) : "f"(x)); return r;
}
__device__ __forceinline__ float2 unpk(unsigned long long v) {
    float2 f; asm("mov.b64 {%0, %1}, %2;" : "=f"(f.x), "=f"(f.y) : "l"(v)); return f;
}

#define GEMM_STEP(ACC, APTR, BPTR) do {                                        \
    float4 a4_ = *reinterpret_cast<const float4*>(APTR);                        \
    ulonglong2 bb_ = *reinterpret_cast<const ulonglong2*>(BPTR);                \
    unsigned long long s_;                                                      \
    s_ = splat2(a4_.x); ffma2(ACC[0][0], s_, bb_.x); ffma2(ACC[0][1], s_, bb_.y); \
    s_ = splat2(a4_.y); ffma2(ACC[1][0], s_, bb_.x); ffma2(ACC[1][1], s_, bb_.y); \
    s_ = splat2(a4_.z); ffma2(ACC[2][0], s_, bb_.x); ffma2(ACC[2][1], s_, bb_.y); \
    s_ = splat2(a4_.w); ffma2(ACC[3][0], s_, bb_.x); ffma2(ACC[3][1], s_, bb_.y); \
} while (0)

// ---------------- prep kernels ----------------
__global__ void prep_edges(const int* __restrict__ ei, const float* __restrict__ pos) {
    int i = blockIdx.x * 256 + threadIdx.x;
    if (i >= NE) return;
    int s = ei[i];
    int d = ei[NE + i];
    // defensive clamp: if index dtype assumption is wrong we want a finite
    // rel_err diagnostic, not an illegal access
    s = min(max(s, 0), NN - 1);
    d = min(max(d, 0), NN - 1);
    g_src[i] = s;
    g_dst[i] = d;
    const float* ps = pos + 3 * (size_t)s;
    const float* pd = pos + 3 * (size_t)d;
    g_evec[3 * (size_t)i + 0] = pd[0] - ps[0];
    g_evec[3 * (size_t)i + 1] = pd[1] - ps[1];
    g_evec[3 * (size_t)i + 2] = pd[2] - ps[2];
}

__global__ void prep_w1eff(const float* __restrict__ ew1, const float* __restrict__ eew) {
    int idx = blockIdx.x * 256 + threadIdx.x;
    if (idx >= NL * 132 * 64) return;
    int j = idx & 63;
    int r = (idx >> 6) % 132;
    int l = idx / (132 * 64);
    float v = 0.f;
    if (r < 128) {
        v = ew1[(size_t)l * 192 * 64 + (size_t)r * 64 + j];
    } else if (r < 131) {
        int c = r - 128;
        const float* w = ew1 + (size_t)l * 192 * 64 + 128 * 64 + j;
        #pragma unroll 8
        for (int m = 0; m < 64; m++) v += eew[c * 64 + m] * w[(size_t)m * 64];
    }
    g_w1eff[l][r * 64 + j] = v;
}

__global__ void prep_b1eff(const float* __restrict__ ew1, const float* __restrict__ eeb,
                           const float* __restrict__ eb1) {
    int idx = blockIdx.x * 64 + threadIdx.x;
    if (idx >= NL * 64) return;
    int j = idx & 63;
    int l = idx >> 6;
    float v = eb1[l * 64 + j];
    const float* w = ew1 + (size_t)l * 192 * 64 + 128 * 64 + j;
    #pragma unroll 8
    for (int m = 0; m < 64; m++) v += eeb[m] * w[(size_t)m * 64];
    g_b1eff[l][j] = v;
}

__global__ void encoder(const float* __restrict__ nf, const float* __restrict__ w,
                        const float* __restrict__ b) {
    int idx = blockIdx.x * 256 + threadIdx.x;
    if (idx >= NN * HD) return;
    int j = idx & 63;
    int n = idx >> 6;
    float acc = b[j];
    acc += nf[n * 3 + 0] * w[j] + nf[n * 3 + 1] * w[64 + j] + nf[n * 3 + 2] * w[128 + j];
    g_h[0][idx] = acc;
}

__global__ void zero_agg() {
    int idx = blockIdx.x * 256 + threadIdx.x;
    if (idx < NN * HD / 4) reinterpret_cast<float4*>(g_agg)[idx] = make_float4(0.f, 0.f, 0.f, 0.f);
}

// ---------------- edge MLP + scatter (fused) ----------------
// CTA: 64 edges x 64 outputs. smem: As[132][68] (overlaid by Hs[64][68]) + W1s[132][64] + W2s[64][64] + Ds[64]
__global__ __launch_bounds__(256, 2)
void edge_kernel(const float* __restrict__ ew2, const float* __restrict__ eb2, int l) {
    extern __shared__ float sm[];
    float* As  = sm;                         // 132*68 = 8976
    float* W1s = sm + 132 * AS_LD;           // 8448
    float* W2s = W1s + 132 * 64;             // 4096
    int*   Ds  = reinterpret_cast<int*>(W2s + 64 * 64);

    const float* hc = g_h[l & 1];
    int tid = threadIdx.x;
    int ebase = blockIdx.x * 64;

    // stage weights
    {
        const float4* s1 = reinterpret_cast<const float4*>(g_w1eff[l]);
        float4* d1 = reinterpret_cast<float4*>(W1s);
        for (int i = tid; i < 132 * 64 / 4; i += 256) d1[i] = s1[i];
        const float4* s2 = reinterpret_cast<const float4*>(ew2 + (size_t)l * 64 * 64);
        float4* d2 = reinterpret_cast<float4*>(W2s);
        for (int i = tid; i < 64 * 64 / 4; i += 256) d2[i] = s2[i];
    }

    // gather: As[k][e], rows 0..63 = h[src], 64..127 = h[dst], 128..130 = evec, 131 = 0
    {
        int e = tid & 63;
        int c0 = tid >> 6;        // 0..3
        int ee = ebase + e;
        int s = g_src[ee];
        int d = g_dst[ee];
        const float4* hs = reinterpret_cast<const float4*>(hc + (size_t)s * HD);
        const float4* hd = reinterpret_cast<const float4*>(hc + (size_t)d * HD);
        #pragma unroll
        for (int c = c0; c < 16; c += 4) {
            float4 v = hs[c];
            As[(4 * c + 0) * AS_LD + e] = v.x;
            As[(4 * c + 1) * AS_LD + e] = v.y;
            As[(4 * c + 2) * AS_LD + e] = v.z;
            As[(4 * c + 3) * AS_LD + e] = v.w;
            float4 w = hd[c];
            As[(64 + 4 * c + 0) * AS_LD + e] = w.x;
            As[(64 + 4 * c + 1) * AS_LD + e] = w.y;
            As[(64 + 4 * c + 2) * AS_LD + e] = w.z;
            As[(64 + 4 * c + 3) * AS_LD + e] = w.w;
        }
        if (c0 == 0) {
            As[128 * AS_LD + e] = g_evec[3 * (size_t)ee + 0];
            As[129 * AS_LD + e] = g_evec[3 * (size_t)ee + 1];
            As[130 * AS_LD + e] = g_evec[3 * (size_t)ee + 2];
            As[131 * AS_LD + e] = 0.f;
            Ds[e] = d;
        }
    }
    __syncthreads();

    int tx4 = (tid & 15) * 4;   // edge micro-tile
    int ty4 = (tid >> 4) * 4;   // output micro-tile

    // GEMM1: [64e x 132k] @ [132k x 64h]
    unsigned long long acc[4][2] = {};
    #pragma unroll 4
    for (int k = 0; k < 132; ++k)
        GEMM_STEP(acc, As + k * AS_LD + tx4, W1s + k * 64 + ty4);

    float hid[4][4];
    {
        float2 bA = *reinterpret_cast<const float2*>(g_b1eff[l] + ty4);
        float2 bB = *reinterpret_cast<const float2*>(g_b1eff[l] + ty4 + 2);
        #pragma unroll
        for (int i = 0; i < 4; i++) {
            float2 u = unpk(acc[i][0]);
            float2 v = unpk(acc[i][1]);
            hid[i][0] = fmaxf(u.x + bA.x, 0.f);
            hid[i][1] = fmaxf(u.y + bA.y, 0.f);
            hid[i][2] = fmaxf(v.x + bB.x, 0.f);
            hid[i][3] = fmaxf(v.y + bB.y, 0.f);
        }
    }
    __syncthreads();            // done reading As
    float* Hs = As;             // overlay: Hs[h][e], 64 x AS_LD
    #pragma unroll
    for (int j = 0; j < 4; j++)
        *reinterpret_cast<float4*>(Hs + (ty4 + j) * AS_LD + tx4) =
            make_float4(hid[0][j], hid[1][j], hid[2][j], hid[3][j]);
    __syncthreads();

    // GEMM2: [64e x 64k] @ [64k x 64h]
    unsigned long long acc2[4][2] = {};
    #pragma unroll 4
    for (int k = 0; k < 64; ++k)
        GEMM_STEP(acc2, Hs + k * AS_LD + tx4, W2s + k * 64 + ty4);

    float2 bA = *reinterpret_cast<const float2*>(eb2 + (size_t)l * 64 + ty4);
    float2 bB = *reinterpret_cast<const float2*>(eb2 + (size_t)l * 64 + ty4 + 2);
    #pragma unroll
    for (int i = 0; i < 4; i++) {
        float2 u = unpk(acc2[i][0]);
        float2 v = unpk(acc2[i][1]);
        float m0 = u.x + bA.x, m1 = u.y + bA.y, m2 = v.x + bB.x, m3 = v.y + bB.y;
        float* addr = g_agg + (size_t)Ds[tx4 + i] * HD + ty4;
        asm volatile("red.global.add.v4.f32 [%0], {%1, %2, %3, %4};"
                     :: "l"(addr), "f"(m0), "f"(m1), "f"(m2), "f"(m3) : "memory");
    }
}

// ---------------- node MLP ----------------
__global__ __launch_bounds__(256, 2)
void node_kernel(const float* __restrict__ nw1, const float* __restrict__ nb1,
                 const float* __restrict__ nw2, const float* __restrict__ nb2, int l) {
    extern __shared__ float sm[];
    float* As  = sm;                   // 128*68 = 8704
    float* W1s = sm + 128 * AS_LD;     // 8192
    float* W2s = W1s + 128 * 64;       // 4096

    const float* hc = g_h[l & 1];
    float* hn = g_h[(l + 1) & 1];
    int tid = threadIdx.x;
    int nbase = blockIdx.x * 64;

    {
        const float4* s1 = reinterpret_cast<const float4*>(nw1 + (size_t)l * 128 * 64);
        float4* d1 = reinterpret_cast<float4*>(W1s);
        for (int i = tid; i < 128 * 64 / 4; i += 256) d1[i] = s1[i];
        const float4* s2 = reinterpret_cast<const float4*>(nw2 + (size_t)l * 64 * 64);
        float4* d2 = reinterpret_cast<float4*>(W2s);
        for (int i = tid; i < 64 * 64 / 4; i += 256) d2[i] = s2[i];
    }

    // gather: rows 0..63 = h, 64..127 = agg (contiguous rows)
    {
        int n = tid & 63;
        int c0 = tid >> 6;
        int node = nbase + n;
        bool valid = node < NN;
        int nclamp = valid ? node : (NN - 1);
        const float4* hp = reinterpret_cast<const float4*>(hc + (size_t)nclamp * HD);
        const float4* ap = reinterpret_cast<const float4*>(g_agg + (size_t)nclamp * HD);
        float4 z = make_float4(0.f, 0.f, 0.f, 0.f);
        #pragma unroll
        for (int c = c0; c < 16; c += 4) {
            float4 v = valid ? hp[c] : z;
            As[(4 * c + 0) * AS_LD + n] = v.x;
            As[(4 * c + 1) * AS_LD + n] = v.y;
            As[(4 * c + 2) * AS_LD + n] = v.z;
            As[(4 * c + 3) * AS_LD + n] = v.w;
            float4 w = valid ? ap[c] : z;
            As[(64 + 4 * c + 0) * AS_LD + n] = w.x;
            As[(64 + 4 * c + 1) * AS_LD + n] = w.y;
            As[(64 + 4 * c + 2) * AS_LD + n] = w.z;
            As[(64 + 4 * c + 3) * AS_LD + n] = w.w;
        }
    }
    __syncthreads();

    int tx4 = (tid & 15) * 4;
    int ty4 = (tid >> 4) * 4;

    unsigned long long acc[4][2] = {};
    #pragma unroll 4
    for (int k = 0; k < 128; ++k)
        GEMM_STEP(acc, As + k * AS_LD + tx4, W1s + k * 64 + ty4);

    float hid[4][4];
    {
        float2 bA = *reinterpret_cast<const float2*>(nb1 + (size_t)l * 64 + ty4);
        float2 bB = *reinterpret_cast<const float2*>(nb1 + (size_t)l * 64 + ty4 + 2);
        #pragma unroll
        for (int i = 0; i < 4; i++) {
            float2 u = unpk(acc[i][0]);
            float2 v = unpk(acc[i][1]);
            hid[i][0] = fmaxf(u.x + bA.x, 0.f);
            hid[i][1] = fmaxf(u.y + bA.y, 0.f);
            hid[i][2] = fmaxf(v.x + bB.x, 0.f);
            hid[i][3] = fmaxf(v.y + bB.y, 0.f);
        }
    }
    __syncthreads();
    float* Hs = As;
    #pragma unroll
    for (int j = 0; j < 4; j++)
        *reinterpret_cast<float4*>(Hs + (ty4 + j) * AS_LD + tx4) =
            make_float4(hid[0][j], hid[1][j], hid[2][j], hid[3][j]);
    __syncthreads();

    unsigned long long acc2[4][2] = {};
    #pragma unroll 4
    for (int k = 0; k < 64; ++k)
        GEMM_STEP(acc2, Hs + k * AS_LD + tx4, W2s + k * 64 + ty4);

    float2 bA = *reinterpret_cast<const float2*>(nb2 + (size_t)l * 64 + ty4);
    float2 bB = *reinterpret_cast<const float2*>(nb2 + (size_t)l * 64 + ty4 + 2);
    #pragma unroll
    for (int i = 0; i < 4; i++) {
        int node = nbase + tx4 + i;
        if (node < NN) {
            float2 u = unpk(acc2[i][0]);
            float2 v = unpk(acc2[i][1]);
            *reinterpret_cast<float4*>(hn + (size_t)node * HD + ty4) =
                make_float4(u.x + bA.x, u.y + bA.y, v.x + bB.x, v.y + bB.y);
        }
    }
}

// ---------------- decoder ----------------
__global__ void decoder(const float* __restrict__ dw, const float* __restrict__ db,
                        float* __restrict__ out) {
    int gid = blockIdx.x * 256 + threadIdx.x;
    int w = gid >> 5, lane = gid & 31;
    if (w >= NN) return;
    const float* hr = g_h[0] + (size_t)w * HD;   // after L=4 layers result is in buffer 0
    float v = hr[lane] * dw[lane] + hr[lane + 32] * dw[lane + 32];
    #pragma unroll
    for (int o = 16; o > 0; o >>= 1) v += __shfl_down_sync(0xffffffffu, v, o);
    if (lane == 0) out[w] = v + db[0];
}

// ---------------- launch ----------------
static constexpr int EDGE_SMEM = (132 * AS_LD + 132 * 64 + 64 * 64) * 4 + 64 * 4; // 86336
static constexpr int NODE_SMEM = (128 * AS_LD + 128 * 64 + 64 * 64) * 4;          // 83968

extern "C" void kernel_launch(void* const* d_in, const int* in_sizes, int n_in,
                              void* d_out, int out_size) {
    const float* node_pos  = (const float*)d_in[0];
    const float* node_feat = (const float*)d_in[1];
    const int*   eidx      = (const int*)d_in[2];     // int32 (JAX x64 disabled)
    const float* enc_w = (const float*)d_in[3];
    const float* enc_b = (const float*)d_in[4];
    const float* eew   = (const float*)d_in[5];
    const float* eeb   = (const float*)d_in[6];
    const float* ew1   = (const float*)d_in[7];
    const float* eb1   = (const float*)d_in[8];
    const float* ew2   = (const float*)d_in[9];
    const float* eb2   = (const float*)d_in[10];
    const float* nw1   = (const float*)d_in[11];
    const float* nb1   = (const float*)d_in[12];
    const float* nw2   = (const float*)d_in[13];
    const float* nb2   = (const float*)d_in[14];
    const float* dec_w = (const float*)d_in[15];
    const float* dec_b = (const float*)d_in[16];
    float* out = (float*)d_out;

    cudaFuncSetAttribute(edge_kernel, cudaFuncAttributeMaxDynamicSharedMemorySize, EDGE_SMEM);
    cudaFuncSetAttribute(node_kernel, cudaFuncAttributeMaxDynamicSharedMemorySize, NODE_SMEM);

    prep_edges<<<(NE + 255) / 256, 256>>>(eidx, node_pos);
    prep_w1eff<<<(NL * 132 * 64 + 255) / 256, 256>>>(ew1, eew);
    prep_b1eff<<<NL, 64>>>(ew1, eeb, eb1);
    encoder<<<(NN * HD + 255) / 256, 256>>>(node_feat, enc_w, enc_b);

    for (int l = 0; l < NL; ++l) {
        zero_agg<<<(NN * HD / 4 + 255) / 256, 256>>>();
        edge_kernel<<<NE / 64, 256, EDGE_SMEM>>>(ew2, eb2, l);
        node_kernel<<<(NN + 63) / 64, 256, NODE_SMEM>>>(nw1, nb1, nw2, nb2, l);
    }

    decoder<<<(NN * 32 + 255) / 256, 256>>>(dec_w, dec_b, out);
}

// round 7
// speedup vs baseline: 4.0827x; 4.0827x over previous
#include <cuda_runtime.h>

#define NN 50000
#define NE 800000
#define HD 64
#define NL 4
#define AS_LD 68

// ---------------- device scratch ----------------
__device__ __align__(16) float g_h[2][(size_t)NN * HD];
__device__ __align__(16) float g_S[(size_t)NN * HD];        // sum of relu(pre1) per node
__device__ __align__(16) float g_uv[(size_t)NN * 128];      // u (cols 0-63), v (cols 64-127)
__device__ __align__(16) float g_deg[NN];                   // in-degree (exact small ints in fp32)
__device__ __align__(16) int   g_src[NE];
__device__ __align__(16) int   g_dst[NE];
__device__ __align__(16) float4 g_evec4[NE];
__device__ __align__(16) float g_wfold[NL][3 * 64];         // edge_enc_w @ W1_e
__device__ __align__(16) float g_b1eff[NL][64];             // b1 + eeb @ W1_e
__device__ __align__(16) float g_wuv[NL][64 * 128];         // [W1a | W1b]
__device__ __align__(16) float g_nwf[NL][128 * 64];         // [M1_top ; W2 @ M1_bot]
__device__ __align__(16) float g_q[NL][64];                 // b2 @ M1_bot

// ---------------- f32x2 packed-FMA helpers ----------------
__device__ __forceinline__ void ffma2(unsigned long long& d, unsigned long long a, unsigned long long b) {
    asm("fma.rn.f32x2 %0, %1, %2, %0;" : "+l"(d) : "l"(a), "l"(b));
}
__device__ __forceinline__ unsigned long long splat2(float x) {
    unsigned long long r; asm("mov.b64 %0, {%1, %1};" : "=l"(r) : "f"(x)); return r;
}
__device__ __forceinline__ float2 unpk(unsigned long long v) {
    float2 f; asm("mov.b64 {%0, %1}, %2;" : "=f"(f.x), "=f"(f.y) : "l"(v)); return f;
}

#define GEMM_STEP(ACC, APTR, BPTR) do {                                        \
    float4 a4_ = *reinterpret_cast<const float4*>(APTR);                        \
    ulonglong2 bb_ = *reinterpret_cast<const ulonglong2*>(BPTR);                \
    unsigned long long s_;                                                      \
    s_ = splat2(a4_.x); ffma2(ACC[0][0], s_, bb_.x); ffma2(ACC[0][1], s_, bb_.y); \
    s_ = splat2(a4_.y); ffma2(ACC[1][0], s_, bb_.x); ffma2(ACC[1][1], s_, bb_.y); \
    s_ = splat2(a4_.z); ffma2(ACC[2][0], s_, bb_.x); ffma2(ACC[2][1], s_, bb_.y); \
    s_ = splat2(a4_.w); ffma2(ACC[3][0], s_, bb_.x); ffma2(ACC[3][1], s_, bb_.y); \
} while (0)

// dual-B variant: one A load feeding two output column blocks
#define GEMM_STEP2(ACU, ACV, APTR, BU, BV) do {                                \
    float4 a4_ = *reinterpret_cast<const float4*>(APTR);                        \
    ulonglong2 bu_ = *reinterpret_cast<const ulonglong2*>(BU);                  \
    ulonglong2 bv_ = *reinterpret_cast<const ulonglong2*>(BV);                  \
    unsigned long long s_;                                                      \
    s_ = splat2(a4_.x); ffma2(ACU[0][0], s_, bu_.x); ffma2(ACU[0][1], s_, bu_.y); ffma2(ACV[0][0], s_, bv_.x); ffma2(ACV[0][1], s_, bv_.y); \
    s_ = splat2(a4_.y); ffma2(ACU[1][0], s_, bu_.x); ffma2(ACU[1][1], s_, bu_.y); ffma2(ACV[1][0], s_, bv_.x); ffma2(ACV[1][1], s_, bv_.y); \
    s_ = splat2(a4_.z); ffma2(ACU[2][0], s_, bu_.x); ffma2(ACU[2][1], s_, bu_.y); ffma2(ACV[2][0], s_, bv_.x); ffma2(ACV[2][1], s_, bv_.y); \
    s_ = splat2(a4_.w); ffma2(ACU[3][0], s_, bu_.x); ffma2(ACU[3][1], s_, bu_.y); ffma2(ACV[3][0], s_, bv_.x); ffma2(ACV[3][1], s_, bv_.y); \
} while (0)

// ---------------- prep kernels ----------------
__global__ void zero_deg() {
    int i = blockIdx.x * 256 + threadIdx.x;
    if (i < NN) g_deg[i] = 0.f;
}

__global__ void prep_edges(const int* __restrict__ ei, const float* __restrict__ pos) {
    int i = blockIdx.x * 256 + threadIdx.x;
    if (i >= NE) return;
    int s = min(max(ei[i], 0), NN - 1);
    int d = min(max(ei[NE + i], 0), NN - 1);
    g_src[i] = s;
    g_dst[i] = d;
    const float* ps = pos + 3 * (size_t)s;
    const float* pd = pos + 3 * (size_t)d;
    g_evec4[i] = make_float4(pd[0] - ps[0], pd[1] - ps[1], pd[2] - ps[2], 0.f);
    atomicAdd(&g_deg[d], 1.f);
}

// wfold[l][c][j] = sum_m eew[c][m] * ew1[l][(128+m)][j]
__global__ void prep_wfold(const float* __restrict__ ew1, const float* __restrict__ eew) {
    int idx = blockIdx.x * 192 + threadIdx.x;   // NL*3*64 threads, block 192
    if (idx >= NL * 3 * 64) return;
    int j = idx & 63;
    int c = (idx >> 6) % 3;
    int l = idx / 192;
    const float* w = ew1 + (size_t)l * 192 * 64 + 128 * 64 + j;
    float v = 0.f;
    #pragma unroll 8
    for (int m = 0; m < 64; m++) v += eew[c * 64 + m] * w[(size_t)m * 64];
    g_wfold[l][c * 64 + j] = v;
}

__global__ void prep_b1eff(const float* __restrict__ ew1, const float* __restrict__ eeb,
                           const float* __restrict__ eb1) {
    int idx = blockIdx.x * 64 + threadIdx.x;
    if (idx >= NL * 64) return;
    int j = idx & 63;
    int l = idx >> 6;
    float v = eb1[l * 64 + j];
    const float* w = ew1 + (size_t)l * 192 * 64 + 128 * 64 + j;
    #pragma unroll 8
    for (int m = 0; m < 64; m++) v += eeb[m] * w[(size_t)m * 64];
    g_b1eff[l][j] = v;
}

// wuv[l][k][j]: j<64 -> W1a[k][j]; j>=64 -> W1b[k][j-64]
__global__ void prep_wuv(const float* __restrict__ ew1) {
    int idx = blockIdx.x * 256 + threadIdx.x;
    if (idx >= NL * 64 * 128) return;
    int j = idx & 127;
    int k = (idx >> 7) & 63;
    int l = idx >> 13;
    const float* base = ew1 + (size_t)l * 192 * 64;
    g_wuv[l][k * 128 + j] = (j < 64) ? base[k * 64 + j] : base[(64 + k) * 64 + (j - 64)];
}

// nwf[l][k][j]: k<64 -> M1_top[k][j]; k>=64 -> (W2 @ M1_bot)[k-64][j]
__global__ void prep_nwf(const float* __restrict__ nw1, const float* __restrict__ ew2) {
    int idx = blockIdx.x * 256 + threadIdx.x;
    if (idx >= NL * 128 * 64) return;
    int j = idx & 63;
    int k = (idx >> 6) & 127;
    int l = idx >> 13;
    const float* m1 = nw1 + (size_t)l * 128 * 64;
    float v;
    if (k < 64) {
        v = m1[k * 64 + j];
    } else {
        int p = k - 64;
        const float* w2 = ew2 + (size_t)l * 64 * 64 + p * 64;
        v = 0.f;
        #pragma unroll 8
        for (int m = 0; m < 64; m++) v += w2[m] * m1[(64 + m) * 64 + j];
    }
    g_nwf[l][k * 64 + j] = v;
}

// q[l][j] = sum_m b2[m] * M1_bot[m][j]
__global__ void prep_q(const float* __restrict__ nw1, const float* __restrict__ eb2) {
    int idx = blockIdx.x * 64 + threadIdx.x;
    if (idx >= NL * 64) return;
    int j = idx & 63;
    int l = idx >> 6;
    const float* m1 = nw1 + (size_t)l * 128 * 64;
    float v = 0.f;
    #pragma unroll 8
    for (int m = 0; m < 64; m++) v += eb2[l * 64 + m] * m1[(64 + m) * 64 + j];
    g_q[l][j] = v;
}

__global__ void encoder(const float* __restrict__ nf, const float* __restrict__ w,
                        const float* __restrict__ b) {
    int idx = blockIdx.x * 256 + threadIdx.x;
    if (idx >= NN * HD) return;
    int j = idx & 63;
    int n = idx >> 6;
    float acc = b[j];
    acc += nf[n * 3 + 0] * w[j] + nf[n * 3 + 1] * w[64 + j] + nf[n * 3 + 2] * w[128 + j];
    g_h[0][idx] = acc;
}

__global__ void zero_S() {
    int idx = blockIdx.x * 256 + threadIdx.x;
    if (idx < NN * HD / 4) reinterpret_cast<float4*>(g_S)[idx] = make_float4(0.f, 0.f, 0.f, 0.f);
}

// ---------------- uv kernel: uv[n] = h[n] @ [W1a|W1b] ----------------
// CTA: 64 nodes x 128 cols, K=64
static constexpr int UV_SMEM = (64 * AS_LD + 64 * 128) * 4;   // 50176
__global__ __launch_bounds__(256)
void uv_kernel(int l) {
    extern __shared__ float sm[];
    float* As = sm;                 // 64 x AS_LD (K-major)
    float* Bs = sm + 64 * AS_LD;    // 64 x 128
    const float* hc = g_h[l & 1];
    int tid = threadIdx.x;
    int nbase = blockIdx.x * 64;

    {
        const float4* s = reinterpret_cast<const float4*>(g_wuv[l]);
        float4* d = reinterpret_cast<float4*>(Bs);
        for (int i = tid; i < 64 * 128 / 4; i += 256) d[i] = s[i];
    }
    {
        int n = tid & 63;
        int c0 = tid >> 6;
        int node = nbase + n;
        bool valid = node < NN;
        int ncl = valid ? node : (NN - 1);
        const float4* hp = reinterpret_cast<const float4*>(hc + (size_t)ncl * HD);
        float4 z = make_float4(0.f, 0.f, 0.f, 0.f);
        #pragma unroll
        for (int c = c0; c < 16; c += 4) {
            float4 v = valid ? hp[c] : z;
            As[(4 * c + 0) * AS_LD + n] = v.x;
            As[(4 * c + 1) * AS_LD + n] = v.y;
            As[(4 * c + 2) * AS_LD + n] = v.z;
            As[(4 * c + 3) * AS_LD + n] = v.w;
        }
    }
    __syncthreads();

    int tx4 = (tid & 15) * 4;
    int ty4 = (tid >> 4) * 4;
    unsigned long long acu[4][2] = {}, acv[4][2] = {};
    #pragma unroll 4
    for (int k = 0; k < 64; ++k)
        GEMM_STEP2(acu, acv, As + k * AS_LD + tx4, Bs + k * 128 + ty4, Bs + k * 128 + 64 + ty4);

    #pragma unroll
    for (int i = 0; i < 4; i++) {
        int node = nbase + tx4 + i;
        if (node < NN) {
            float2 u0 = unpk(acu[i][0]), u1 = unpk(acu[i][1]);
            float2 v0 = unpk(acv[i][0]), v1 = unpk(acv[i][1]);
            *reinterpret_cast<float4*>(g_uv + (size_t)node * 128 + ty4)      = make_float4(u0.x, u0.y, u1.x, u1.y);
            *reinterpret_cast<float4*>(g_uv + (size_t)node * 128 + 64 + ty4) = make_float4(v0.x, v0.y, v1.x, v1.y);
        }
    }
}

// ---------------- edge scatter: S[dst] += relu(u[src]+v[dst]+evec@wfold+b1eff) ----------------
// 16 threads per edge, 4 cols each
__global__ __launch_bounds__(256)
void edge_scatter(int l) {
    int g = blockIdx.x * 256 + threadIdx.x;   // < NE*16
    int e = g >> 4;
    int c4 = (g & 15) * 4;
    int s = g_src[e];
    int d = g_dst[e];
    float4 uu = *reinterpret_cast<const float4*>(g_uv + (size_t)s * 128 + c4);
    float4 vv = *reinterpret_cast<const float4*>(g_uv + (size_t)d * 128 + 64 + c4);
    float4 ev = g_evec4[e];
    const float* wf = g_wfold[l];
    float4 w0 = *reinterpret_cast<const float4*>(wf + c4);
    float4 w1 = *reinterpret_cast<const float4*>(wf + 64 + c4);
    float4 w2 = *reinterpret_cast<const float4*>(wf + 128 + c4);
    float4 b  = *reinterpret_cast<const float4*>(g_b1eff[l] + c4);
    float r0 = fmaxf(fmaf(ev.x, w0.x, fmaf(ev.y, w1.x, fmaf(ev.z, w2.x, uu.x + vv.x + b.x))), 0.f);
    float r1 = fmaxf(fmaf(ev.x, w0.y, fmaf(ev.y, w1.y, fmaf(ev.z, w2.y, uu.y + vv.y + b.y))), 0.f);
    float r2 = fmaxf(fmaf(ev.x, w0.z, fmaf(ev.y, w1.z, fmaf(ev.z, w2.z, uu.z + vv.z + b.z))), 0.f);
    float r3 = fmaxf(fmaf(ev.x, w0.w, fmaf(ev.y, w1.w, fmaf(ev.z, w2.w, uu.w + vv.w + b.w))), 0.f);
    float* addr = g_S + (size_t)d * HD + c4;
    asm volatile("red.global.add.v4.f32 [%0], {%1, %2, %3, %4};"
                 :: "l"(addr), "f"(r0), "f"(r1), "f"(r2), "f"(r3) : "memory");
}

// ---------------- node MLP (fused agg): out = relu([h|S]@nwf + deg*q + c1)@M2 + c2 ----------------
static constexpr int NODE_SMEM = (128 * AS_LD + 128 * 64 + 64 * 64 + 64 + 64) * 4;  // 84480
__global__ __launch_bounds__(256, 2)
void node_kernel(const float* __restrict__ nb1, const float* __restrict__ nw2,
                 const float* __restrict__ nb2, int l) {
    extern __shared__ float sm[];
    float* As  = sm;                        // 128 x AS_LD
    float* W1s = sm + 128 * AS_LD;          // 128 x 64 (nwf)
    float* W2s = W1s + 128 * 64;            // 64 x 64
    float* qs  = W2s + 64 * 64;             // 64
    float* Dg  = qs + 64;                   // 64

    const float* hc = g_h[l & 1];
    float* hn = g_h[(l + 1) & 1];
    int tid = threadIdx.x;
    int nbase = blockIdx.x * 64;

    {
        const float4* s1 = reinterpret_cast<const float4*>(g_nwf[l]);
        float4* d1 = reinterpret_cast<float4*>(W1s);
        for (int i = tid; i < 128 * 64 / 4; i += 256) d1[i] = s1[i];
        const float4* s2 = reinterpret_cast<const float4*>(nw2 + (size_t)l * 64 * 64);
        float4* d2 = reinterpret_cast<float4*>(W2s);
        for (int i = tid; i < 64 * 64 / 4; i += 256) d2[i] = s2[i];
        if (tid < 64) {
            qs[tid] = g_q[l][tid];
            int node = nbase + tid;
            Dg[tid] = (node < NN) ? g_deg[node] : 0.f;
        }
    }

    {
        int n = tid & 63;
        int c0 = tid >> 6;
        int node = nbase + n;
        bool valid = node < NN;
        int ncl = valid ? node : (NN - 1);
        const float4* hp = reinterpret_cast<const float4*>(hc + (size_t)ncl * HD);
        const float4* ap = reinterpret_cast<const float4*>(g_S + (size_t)ncl * HD);
        float4 z = make_float4(0.f, 0.f, 0.f, 0.f);
        #pragma unroll
        for (int c = c0; c < 16; c += 4) {
            float4 v = valid ? hp[c] : z;
            As[(4 * c + 0) * AS_LD + n] = v.x;
            As[(4 * c + 1) * AS_LD + n] = v.y;
            As[(4 * c + 2) * AS_LD + n] = v.z;
            As[(4 * c + 3) * AS_LD + n] = v.w;
            float4 w = valid ? ap[c] : z;
            As[(64 + 4 * c + 0) * AS_LD + n] = w.x;
            As[(64 + 4 * c + 1) * AS_LD + n] = w.y;
            As[(64 + 4 * c + 2) * AS_LD + n] = w.z;
            As[(64 + 4 * c + 3) * AS_LD + n] = w.w;
        }
    }
    __syncthreads();

    int tx4 = (tid & 15) * 4;
    int ty4 = (tid >> 4) * 4;

    unsigned long long acc[4][2] = {};
    #pragma unroll 4
    for (int k = 0; k < 128; ++k)
        GEMM_STEP(acc, As + k * AS_LD + tx4, W1s + k * 64 + ty4);

    float hid[4][4];
    {
        float2 bA = *reinterpret_cast<const float2*>(nb1 + (size_t)l * 64 + ty4);
        float2 bB = *reinterpret_cast<const float2*>(nb1 + (size_t)l * 64 + ty4 + 2);
        float2 qA = *reinterpret_cast<const float2*>(qs + ty4);
        float2 qB = *reinterpret_cast<const float2*>(qs + ty4 + 2);
        #pragma unroll
        for (int i = 0; i < 4; i++) {
            float dg = Dg[tx4 + i];
            float2 u = unpk(acc[i][0]);
            float2 v = unpk(acc[i][1]);
            hid[i][0] = fmaxf(fmaf(dg, qA.x, u.x + bA.x), 0.f);
            hid[i][1] = fmaxf(fmaf(dg, qA.y, u.y + bA.y), 0.f);
            hid[i][2] = fmaxf(fmaf(dg, qB.x, v.x + bB.x), 0.f);
            hid[i][3] = fmaxf(fmaf(dg, qB.y, v.y + bB.y), 0.f);
        }
    }
    __syncthreads();
    float* Hs = As;
    #pragma unroll
    for (int j = 0; j < 4; j++)
        *reinterpret_cast<float4*>(Hs + (ty4 + j) * AS_LD + tx4) =
            make_float4(hid[0][j], hid[1][j], hid[2][j], hid[3][j]);
    __syncthreads();

    unsigned long long acc2[4][2] = {};
    #pragma unroll 4
    for (int k = 0; k < 64; ++k)
        GEMM_STEP(acc2, Hs + k * AS_LD + tx4, W2s + k * 64 + ty4);

    float2 bA = *reinterpret_cast<const float2*>(nb2 + (size_t)l * 64 + ty4);
    float2 bB = *reinterpret_cast<const float2*>(nb2 + (size_t)l * 64 + ty4 + 2);
    #pragma unroll
    for (int i = 0; i < 4; i++) {
        int node = nbase + tx4 + i;
        if (node < NN) {
            float2 u = unpk(acc2[i][0]);
            float2 v = unpk(acc2[i][1]);
            *reinterpret_cast<float4*>(hn + (size_t)node * HD + ty4) =
                make_float4(u.x + bA.x, u.y + bA.y, v.x + bB.x, v.y + bB.y);
        }
    }
}

// ---------------- decoder ----------------
__global__ void decoder(const float* __restrict__ dw, const float* __restrict__ db,
                        float* __restrict__ out) {
    int gid = blockIdx.x * 256 + threadIdx.x;
    int w = gid >> 5, lane = gid & 31;
    if (w >= NN) return;
    const float* hr = g_h[0] + (size_t)w * HD;
    float v = hr[lane] * dw[lane] + hr[lane + 32] * dw[lane + 32];
    #pragma unroll
    for (int o = 16; o > 0; o >>= 1) v += __shfl_down_sync(0xffffffffu, v, o);
    if (lane == 0) out[w] = v + db[0];
}

// ---------------- launch ----------------
#define NTILES ((NN + 63) / 64)   // 782

extern "C" void kernel_launch(void* const* d_in, const int* in_sizes, int n_in,
                              void* d_out, int out_size) {
    const float* node_pos  = (const float*)d_in[0];
    const float* node_feat = (const float*)d_in[1];
    const int*   eidx      = (const int*)d_in[2];
    const float* enc_w = (const float*)d_in[3];
    const float* enc_b = (const float*)d_in[4];
    const float* eew   = (const float*)d_in[5];
    const float* eeb   = (const float*)d_in[6];
    const float* ew1   = (const float*)d_in[7];
    const float* eb1   = (const float*)d_in[8];
    const float* ew2   = (const float*)d_in[9];
    const float* eb2   = (const float*)d_in[10];
    const float* nw1   = (const float*)d_in[11];
    const float* nb1   = (const float*)d_in[12];
    const float* nw2   = (const float*)d_in[13];
    const float* nb2   = (const float*)d_in[14];
    const float* dec_w = (const float*)d_in[15];
    const float* dec_b = (const float*)d_in[16];
    float* out = (float*)d_out;

    cudaFuncSetAttribute(uv_kernel, cudaFuncAttributeMaxDynamicSharedMemorySize, UV_SMEM);
    cudaFuncSetAttribute(node_kernel, cudaFuncAttributeMaxDynamicSharedMemorySize, NODE_SMEM);

    zero_deg<<<(NN + 255) / 256, 256>>>();
    prep_edges<<<(NE + 255) / 256, 256>>>(eidx, node_pos);
    prep_wfold<<<NL, 192>>>(ew1, eew);
    prep_b1eff<<<NL, 64>>>(ew1, eeb, eb1);
    prep_wuv<<<(NL * 64 * 128 + 255) / 256, 256>>>(ew1);
    prep_nwf<<<(NL * 128 * 64 + 255) / 256, 256>>>(nw1, ew2);
    prep_q<<<NL, 64>>>(nw1, eb2);
    encoder<<<(NN * HD + 255) / 256, 256>>>(node_feat, enc_w, enc_b);

    for (int l = 0; l < NL; ++l) {
        uv_kernel<<<NTILES, 256, UV_SMEM>>>(l);
        zero_S<<<(NN * HD / 4 + 255) / 256, 256>>>();
        edge_scatter<<<NE * 16 / 256, 256>>>(l);
        node_kernel<<<NTILES, 256, NODE_SMEM>>>(nb1, nw2, nb2, l);
    }

    decoder<<<(NN * 32 + 255) / 256, 256>>>(dec_w, dec_b, out);
}

// round 8
// speedup vs baseline: 4.3793x; 1.0726x over previous
#include <cuda_runtime.h>

#define NN 50000
#define NE 800000
#define HD 64
#define NL 4
#define AS_LD 68

// ---------------- device scratch ----------------
__device__ __align__(16) float g_h[2][(size_t)NN * HD];
__device__ __align__(16) float g_S[(size_t)NN * HD];        // segment-summed relu(pre1) per node
__device__ __align__(16) float g_uv[(size_t)NN * 128];      // u (cols 0-63), v (cols 64-127)
__device__ __align__(16) float g_deg[NN];
__device__ __align__(16) int   g_src[NE];
__device__ __align__(16) int   g_dst[NE];
__device__ __align__(16) float4 g_evec4[NE];
// CSR (sorted by dst)
__device__ __align__(16) int   g_cnt[NN];
__device__ __align__(16) int   g_fill[NN];
__device__ __align__(16) int   g_rowptr[NN + 1];
__device__ __align__(16) int   g_src_s[NE];
__device__ __align__(16) float4 g_evec_s[NE];
// folded weights
__device__ __align__(16) float g_wfold[NL][3 * 64];         // edge_enc_w @ W1_e
__device__ __align__(16) float g_b1eff[NL][64];             // b1 + eeb @ W1_e
__device__ __align__(16) float g_wuv[NL][64 * 128];         // [W1a | W1b]
__device__ __align__(16) float g_nwf[NL][128 * 64];         // [M1_top ; W2 @ M1_bot]
__device__ __align__(16) float g_q[NL][64];                 // b2 @ M1_bot

// ---------------- f32x2 packed-FMA helpers ----------------
__device__ __forceinline__ void ffma2(unsigned long long& d, unsigned long long a, unsigned long long b) {
    asm("fma.rn.f32x2 %0, %1, %2, %0;" : "+l"(d) : "l"(a), "l"(b));
}
__device__ __forceinline__ unsigned long long splat2(float x) {
    unsigned long long r; asm("mov.b64 %0, {%1, %1};" : "=l"(r) : "f"(x)); return r;
}
__device__ __forceinline__ float2 unpk(unsigned long long v) {
    float2 f; asm("mov.b64 {%0, %1}, %2;" : "=f"(f.x), "=f"(f.y) : "l"(v)); return f;
}

#define GEMM_STEP(ACC, APTR, BPTR) do {                                        \
    float4 a4_ = *reinterpret_cast<const float4*>(APTR);                        \
    ulonglong2 bb_ = *reinterpret_cast<const ulonglong2*>(BPTR);                \
    unsigned long long s_;                                                      \
    s_ = splat2(a4_.x); ffma2(ACC[0][0], s_, bb_.x); ffma2(ACC[0][1], s_, bb_.y); \
    s_ = splat2(a4_.y); ffma2(ACC[1][0], s_, bb_.x); ffma2(ACC[1][1], s_, bb_.y); \
    s_ = splat2(a4_.z); ffma2(ACC[2][0], s_, bb_.x); ffma2(ACC[2][1], s_, bb_.y); \
    s_ = splat2(a4_.w); ffma2(ACC[3][0], s_, bb_.x); ffma2(ACC[3][1], s_, bb_.y); \
} while (0)

#define GEMM_STEP2(ACU, ACV, APTR, BU, BV) do {                                \
    float4 a4_ = *reinterpret_cast<const float4*>(APTR);                        \
    ulonglong2 bu_ = *reinterpret_cast<const ulonglong2*>(BU);                  \
    ulonglong2 bv_ = *reinterpret_cast<const ulonglong2*>(BV);                  \
    unsigned long long s_;                                                      \
    s_ = splat2(a4_.x); ffma2(ACU[0][0], s_, bu_.x); ffma2(ACU[0][1], s_, bu_.y); ffma2(ACV[0][0], s_, bv_.x); ffma2(ACV[0][1], s_, bv_.y); \
    s_ = splat2(a4_.y); ffma2(ACU[1][0], s_, bu_.x); ffma2(ACU[1][1], s_, bu_.y); ffma2(ACV[1][0], s_, bv_.x); ffma2(ACV[1][1], s_, bv_.y); \
    s_ = splat2(a4_.z); ffma2(ACU[2][0], s_, bu_.x); ffma2(ACU[2][1], s_, bu_.y); ffma2(ACV[2][0], s_, bv_.x); ffma2(ACV[2][1], s_, bv_.y); \
    s_ = splat2(a4_.w); ffma2(ACU[3][0], s_, bu_.x); ffma2(ACU[3][1], s_, bu_.y); ffma2(ACV[3][0], s_, bv_.x); ffma2(ACV[3][1], s_, bv_.y); \
} while (0)

// ---------------- prep kernels ----------------
__global__ void zero_counters() {
    int i = blockIdx.x * 256 + threadIdx.x;
    if (i < NN) { g_deg[i] = 0.f; g_cnt[i] = 0; g_fill[i] = 0; }
}

__global__ void prep_edges(const int* __restrict__ ei, const float* __restrict__ pos) {
    int i = blockIdx.x * 256 + threadIdx.x;
    if (i >= NE) return;
    int s = min(max(ei[i], 0), NN - 1);
    int d = min(max(ei[NE + i], 0), NN - 1);
    g_src[i] = s;
    g_dst[i] = d;
    const float* ps = pos + 3 * (size_t)s;
    const float* pd = pos + 3 * (size_t)d;
    g_evec4[i] = make_float4(pd[0] - ps[0], pd[1] - ps[1], pd[2] - ps[2], 0.f);
    atomicAdd(&g_cnt[d], 1);
    atomicAdd(&g_deg[d], 1.f);
}

// single-block exclusive scan: g_rowptr[0..NN]
#define SCN_C 49   // ceil(50000/1024)
__global__ void scan_counts() {
    __shared__ int part[1024];
    int t = threadIdx.x;
    int base = t * SCN_C;
    int sum = 0;
    for (int i = 0; i < SCN_C; i++) {
        int idx = base + i;
        if (idx < NN) sum += g_cnt[idx];
    }
    part[t] = sum;
    __syncthreads();
    for (int off = 1; off < 1024; off <<= 1) {
        int v = (t >= off) ? part[t - off] : 0;
        __syncthreads();
        if (t >= off) part[t] += v;
        __syncthreads();
    }
    int run = (t > 0) ? part[t - 1] : 0;
    for (int i = 0; i < SCN_C; i++) {
        int idx = base + i;
        if (idx < NN) { g_rowptr[idx] = run; run += g_cnt[idx]; }
    }
    if (t == 1023) g_rowptr[NN] = run;
}

__global__ void fill_csr() {
    int i = blockIdx.x * 256 + threadIdx.x;
    if (i >= NE) return;
    int d = g_dst[i];
    int pos = g_rowptr[d] + atomicAdd(&g_fill[d], 1);
    g_src_s[pos] = g_src[i];
    g_evec_s[pos] = g_evec4[i];
}

// wfold[l][c][j] = sum_m eew[c][m] * ew1[l][(128+m)][j]
__global__ void prep_wfold(const float* __restrict__ ew1, const float* __restrict__ eew) {
    int idx = blockIdx.x * 192 + threadIdx.x;
    if (idx >= NL * 3 * 64) return;
    int j = idx & 63;
    int c = (idx >> 6) % 3;
    int l = idx / 192;
    const float* w = ew1 + (size_t)l * 192 * 64 + 128 * 64 + j;
    float v = 0.f;
    #pragma unroll 8
    for (int m = 0; m < 64; m++) v += eew[c * 64 + m] * w[(size_t)m * 64];
    g_wfold[l][c * 64 + j] = v;
}

__global__ void prep_b1eff(const float* __restrict__ ew1, const float* __restrict__ eeb,
                           const float* __restrict__ eb1) {
    int idx = blockIdx.x * 64 + threadIdx.x;
    if (idx >= NL * 64) return;
    int j = idx & 63;
    int l = idx >> 6;
    float v = eb1[l * 64 + j];
    const float* w = ew1 + (size_t)l * 192 * 64 + 128 * 64 + j;
    #pragma unroll 8
    for (int m = 0; m < 64; m++) v += eeb[m] * w[(size_t)m * 64];
    g_b1eff[l][j] = v;
}

__global__ void prep_wuv(const float* __restrict__ ew1) {
    int idx = blockIdx.x * 256 + threadIdx.x;
    if (idx >= NL * 64 * 128) return;
    int j = idx & 127;
    int k = (idx >> 7) & 63;
    int l = idx >> 13;
    const float* base = ew1 + (size_t)l * 192 * 64;
    g_wuv[l][k * 128 + j] = (j < 64) ? base[k * 64 + j] : base[(64 + k) * 64 + (j - 64)];
}

__global__ void prep_nwf(const float* __restrict__ nw1, const float* __restrict__ ew2) {
    int idx = blockIdx.x * 256 + threadIdx.x;
    if (idx >= NL * 128 * 64) return;
    int j = idx & 63;
    int k = (idx >> 6) & 127;
    int l = idx >> 13;
    const float* m1 = nw1 + (size_t)l * 128 * 64;
    float v;
    if (k < 64) {
        v = m1[k * 64 + j];
    } else {
        int p = k - 64;
        const float* w2 = ew2 + (size_t)l * 64 * 64 + p * 64;
        v = 0.f;
        #pragma unroll 8
        for (int m = 0; m < 64; m++) v += w2[m] * m1[(64 + m) * 64 + j];
    }
    g_nwf[l][k * 64 + j] = v;
}

__global__ void prep_q(const float* __restrict__ nw1, const float* __restrict__ eb2) {
    int idx = blockIdx.x * 64 + threadIdx.x;
    if (idx >= NL * 64) return;
    int j = idx & 63;
    int l = idx >> 6;
    const float* m1 = nw1 + (size_t)l * 128 * 64;
    float v = 0.f;
    #pragma unroll 8
    for (int m = 0; m < 64; m++) v += eb2[l * 64 + m] * m1[(64 + m) * 64 + j];
    g_q[l][j] = v;
}

__global__ void encoder(const float* __restrict__ nf, const float* __restrict__ w,
                        const float* __restrict__ b) {
    int idx = blockIdx.x * 256 + threadIdx.x;
    if (idx >= NN * HD) return;
    int j = idx & 63;
    int n = idx >> 6;
    float acc = b[j];
    acc += nf[n * 3 + 0] * w[j] + nf[n * 3 + 1] * w[64 + j] + nf[n * 3 + 2] * w[128 + j];
    g_h[0][idx] = acc;
}

// ---------------- uv kernel: uv[n] = h[n] @ [W1a|W1b] ----------------
static constexpr int UV_SMEM = (64 * AS_LD + 64 * 128) * 4;   // 50176
__global__ __launch_bounds__(256)
void uv_kernel(int l) {
    extern __shared__ float sm[];
    float* As = sm;
    float* Bs = sm + 64 * AS_LD;
    const float* hc = g_h[l & 1];
    int tid = threadIdx.x;
    int nbase = blockIdx.x * 64;

    {
        const float4* s = reinterpret_cast<const float4*>(g_wuv[l]);
        float4* d = reinterpret_cast<float4*>(Bs);
        for (int i = tid; i < 64 * 128 / 4; i += 256) d[i] = s[i];
    }
    {
        int n = tid & 63;
        int c0 = tid >> 6;
        int node = nbase + n;
        bool valid = node < NN;
        int ncl = valid ? node : (NN - 1);
        const float4* hp = reinterpret_cast<const float4*>(hc + (size_t)ncl * HD);
        float4 z = make_float4(0.f, 0.f, 0.f, 0.f);
        #pragma unroll
        for (int c = c0; c < 16; c += 4) {
            float4 v = valid ? hp[c] : z;
            As[(4 * c + 0) * AS_LD + n] = v.x;
            As[(4 * c + 1) * AS_LD + n] = v.y;
            As[(4 * c + 2) * AS_LD + n] = v.z;
            As[(4 * c + 3) * AS_LD + n] = v.w;
        }
    }
    __syncthreads();

    int tx4 = (tid & 15) * 4;
    int ty4 = (tid >> 4) * 4;
    unsigned long long acu[4][2] = {}, acv[4][2] = {};
    #pragma unroll 4
    for (int k = 0; k < 64; ++k)
        GEMM_STEP2(acu, acv, As + k * AS_LD + tx4, Bs + k * 128 + ty4, Bs + k * 128 + 64 + ty4);

    #pragma unroll
    for (int i = 0; i < 4; i++) {
        int node = nbase + tx4 + i;
        if (node < NN) {
            float2 u0 = unpk(acu[i][0]), u1 = unpk(acu[i][1]);
            float2 v0 = unpk(acv[i][0]), v1 = unpk(acv[i][1]);
            *reinterpret_cast<float4*>(g_uv + (size_t)node * 128 + ty4)      = make_float4(u0.x, u0.y, u1.x, u1.y);
            *reinterpret_cast<float4*>(g_uv + (size_t)node * 128 + 64 + ty4) = make_float4(v0.x, v0.y, v1.x, v1.y);
        }
    }
}

// ---------------- edge gather (CSR segment sum): S[w] = sum_e relu(u[src]+v[w]+ev@wf+b) ----------------
// one warp per dst node, 2 columns per lane, plain store (no atomics)
__global__ __launch_bounds__(256)
void edge_gather(int l) {
    int g = blockIdx.x * 256 + threadIdx.x;
    int w = g >> 5;
    int lane = g & 31;
    if (w >= NN) return;
    int c2 = lane * 2;

    const float* wf = g_wfold[l];
    float2 w0 = *reinterpret_cast<const float2*>(wf + c2);
    float2 w1 = *reinterpret_cast<const float2*>(wf + 64 + c2);
    float2 w2 = *reinterpret_cast<const float2*>(wf + 128 + c2);
    float2 b  = *reinterpret_cast<const float2*>(g_b1eff[l] + c2);
    float2 vv = *reinterpret_cast<const float2*>(g_uv + (size_t)w * 128 + 64 + c2);
    float bx = vv.x + b.x, by = vv.y + b.y;

    int beg = g_rowptr[w];
    int end = g_rowptr[w + 1];
    float ax = 0.f, ay = 0.f;

    // software pipeline: prefetch src/evec/u one iteration ahead
    float4 ev_c;
    float2 uu_c;
    if (beg < end) {
        int s0 = g_src_s[beg];
        ev_c = g_evec_s[beg];
        uu_c = *reinterpret_cast<const float2*>(g_uv + (size_t)s0 * 128 + c2);
    }
    for (int i = beg; i < end; i++) {
        float4 ev = ev_c;
        float2 uu = uu_c;
        if (i + 1 < end) {
            int sn = g_src_s[i + 1];
            ev_c = g_evec_s[i + 1];
            uu_c = *reinterpret_cast<const float2*>(g_uv + (size_t)sn * 128 + c2);
        }
        float p0 = fmaf(ev.x, w0.x, fmaf(ev.y, w1.x, fmaf(ev.z, w2.x, uu.x + bx)));
        float p1 = fmaf(ev.x, w0.y, fmaf(ev.y, w1.y, fmaf(ev.z, w2.y, uu.y + by)));
        ax += fmaxf(p0, 0.f);
        ay += fmaxf(p1, 0.f);
    }
    *reinterpret_cast<float2*>(g_S + (size_t)w * HD + c2) = make_float2(ax, ay);
}

// ---------------- node MLP (fused agg) ----------------
static constexpr int NODE_SMEM = (128 * AS_LD + 128 * 64 + 64 * 64 + 64 + 64) * 4;  // 84480
__global__ __launch_bounds__(256, 2)
void node_kernel(const float* __restrict__ nb1, const float* __restrict__ nw2,
                 const float* __restrict__ nb2, int l) {
    extern __shared__ float sm[];
    float* As  = sm;
    float* W1s = sm + 128 * AS_LD;
    float* W2s = W1s + 128 * 64;
    float* qs  = W2s + 64 * 64;
    float* Dg  = qs + 64;

    const float* hc = g_h[l & 1];
    float* hn = g_h[(l + 1) & 1];
    int tid = threadIdx.x;
    int nbase = blockIdx.x * 64;

    {
        const float4* s1 = reinterpret_cast<const float4*>(g_nwf[l]);
        float4* d1 = reinterpret_cast<float4*>(W1s);
        for (int i = tid; i < 128 * 64 / 4; i += 256) d1[i] = s1[i];
        const float4* s2 = reinterpret_cast<const float4*>(nw2 + (size_t)l * 64 * 64);
        float4* d2 = reinterpret_cast<float4*>(W2s);
        for (int i = tid; i < 64 * 64 / 4; i += 256) d2[i] = s2[i];
        if (tid < 64) {
            qs[tid] = g_q[l][tid];
            int node = nbase + tid;
            Dg[tid] = (node < NN) ? g_deg[node] : 0.f;
        }
    }

    {
        int n = tid & 63;
        int c0 = tid >> 6;
        int node = nbase + n;
        bool valid = node < NN;
        int ncl = valid ? node : (NN - 1);
        const float4* hp = reinterpret_cast<const float4*>(hc + (size_t)ncl * HD);
        const float4* ap = reinterpret_cast<const float4*>(g_S + (size_t)ncl * HD);
        float4 z = make_float4(0.f, 0.f, 0.f, 0.f);
        #pragma unroll
        for (int c = c0; c < 16; c += 4) {
            float4 v = valid ? hp[c] : z;
            As[(4 * c + 0) * AS_LD + n] = v.x;
            As[(4 * c + 1) * AS_LD + n] = v.y;
            As[(4 * c + 2) * AS_LD + n] = v.z;
            As[(4 * c + 3) * AS_LD + n] = v.w;
            float4 w = valid ? ap[c] : z;
            As[(64 + 4 * c + 0) * AS_LD + n] = w.x;
            As[(64 + 4 * c + 1) * AS_LD + n] = w.y;
            As[(64 + 4 * c + 2) * AS_LD + n] = w.z;
            As[(64 + 4 * c + 3) * AS_LD + n] = w.w;
        }
    }
    __syncthreads();

    int tx4 = (tid & 15) * 4;
    int ty4 = (tid >> 4) * 4;

    unsigned long long acc[4][2] = {};
    #pragma unroll 4
    for (int k = 0; k < 128; ++k)
        GEMM_STEP(acc, As + k * AS_LD + tx4, W1s + k * 64 + ty4);

    float hid[4][4];
    {
        float2 bA = *reinterpret_cast<const float2*>(nb1 + (size_t)l * 64 + ty4);
        float2 bB = *reinterpret_cast<const float2*>(nb1 + (size_t)l * 64 + ty4 + 2);
        float2 qA = *reinterpret_cast<const float2*>(qs + ty4);
        float2 qB = *reinterpret_cast<const float2*>(qs + ty4 + 2);
        #pragma unroll
        for (int i = 0; i < 4; i++) {
            float dg = Dg[tx4 + i];
            float2 u = unpk(acc[i][0]);
            float2 v = unpk(acc[i][1]);
            hid[i][0] = fmaxf(fmaf(dg, qA.x, u.x + bA.x), 0.f);
            hid[i][1] = fmaxf(fmaf(dg, qA.y, u.y + bA.y), 0.f);
            hid[i][2] = fmaxf(fmaf(dg, qB.x, v.x + bB.x), 0.f);
            hid[i][3] = fmaxf(fmaf(dg, qB.y, v.y + bB.y), 0.f);
        }
    }
    __syncthreads();
    float* Hs = As;
    #pragma unroll
    for (int j = 0; j < 4; j++)
        *reinterpret_cast<float4*>(Hs + (ty4 + j) * AS_LD + tx4) =
            make_float4(hid[0][j], hid[1][j], hid[2][j], hid[3][j]);
    __syncthreads();

    unsigned long long acc2[4][2] = {};
    #pragma unroll 4
    for (int k = 0; k < 64; ++k)
        GEMM_STEP(acc2, Hs + k * AS_LD + tx4, W2s + k * 64 + ty4);

    float2 bA = *reinterpret_cast<const float2*>(nb2 + (size_t)l * 64 + ty4);
    float2 bB = *reinterpret_cast<const float2*>(nb2 + (size_t)l * 64 + ty4 + 2);
    #pragma unroll
    for (int i = 0; i < 4; i++) {
        int node = nbase + tx4 + i;
        if (node < NN) {
            float2 u = unpk(acc2[i][0]);
            float2 v = unpk(acc2[i][1]);
            *reinterpret_cast<float4*>(hn + (size_t)node * HD + ty4) =
                make_float4(u.x + bA.x, u.y + bA.y, v.x + bB.x, v.y + bB.y);
        }
    }
}

// ---------------- decoder ----------------
__global__ void decoder(const float* __restrict__ dw, const float* __restrict__ db,
                        float* __restrict__ out) {
    int gid = blockIdx.x * 256 + threadIdx.x;
    int w = gid >> 5, lane = gid & 31;
    if (w >= NN) return;
    const float* hr = g_h[0] + (size_t)w * HD;
    float v = hr[lane] * dw[lane] + hr[lane + 32] * dw[lane + 32];
    #pragma unroll
    for (int o = 16; o > 0; o >>= 1) v += __shfl_down_sync(0xffffffffu, v, o);
    if (lane == 0) out[w] = v + db[0];
}

// ---------------- launch ----------------
#define NTILES ((NN + 63) / 64)   // 782

extern "C" void kernel_launch(void* const* d_in, const int* in_sizes, int n_in,
                              void* d_out, int out_size) {
    const float* node_pos  = (const float*)d_in[0];
    const float* node_feat = (const float*)d_in[1];
    const int*   eidx      = (const int*)d_in[2];
    const float* enc_w = (const float*)d_in[3];
    const float* enc_b = (const float*)d_in[4];
    const float* eew   = (const float*)d_in[5];
    const float* eeb   = (const float*)d_in[6];
    const float* ew1   = (const float*)d_in[7];
    const float* eb1   = (const float*)d_in[8];
    const float* ew2   = (const float*)d_in[9];
    const float* eb2   = (const float*)d_in[10];
    const float* nw1   = (const float*)d_in[11];
    const float* nb1   = (const float*)d_in[12];
    const float* nw2   = (const float*)d_in[13];
    const float* nb2   = (const float*)d_in[14];
    const float* dec_w = (const float*)d_in[15];
    const float* dec_b = (const float*)d_in[16];
    float* out = (float*)d_out;

    cudaFuncSetAttribute(uv_kernel, cudaFuncAttributeMaxDynamicSharedMemorySize, UV_SMEM);
    cudaFuncSetAttribute(node_kernel, cudaFuncAttributeMaxDynamicSharedMemorySize, NODE_SMEM);

    zero_counters<<<(NN + 255) / 256, 256>>>();
    prep_edges<<<(NE + 255) / 256, 256>>>(eidx, node_pos);
    scan_counts<<<1, 1024>>>();
    fill_csr<<<(NE + 255) / 256, 256>>>();
    prep_wfold<<<NL, 192>>>(ew1, eew);
    prep_b1eff<<<NL, 64>>>(ew1, eeb, eb1);
    prep_wuv<<<(NL * 64 * 128 + 255) / 256, 256>>>(ew1);
    prep_nwf<<<(NL * 128 * 64 + 255) / 256, 256>>>(nw1, ew2);
    prep_q<<<NL, 64>>>(nw1, eb2);
    encoder<<<(NN * HD + 255) / 256, 256>>>(node_feat, enc_w, enc_b);

    for (int l = 0; l < NL; ++l) {
        uv_kernel<<<NTILES, 256, UV_SMEM>>>(l);
        edge_gather<<<(NN * 32 + 255) / 256, 256>>>(l);
        node_kernel<<<NTILES, 256, NODE_SMEM>>>(nb1, nw2, nb2, l);
    }

    decoder<<<(NN * 32 + 255) / 256, 256>>>(dec_w, dec_b, out);
}

// round 9
// speedup vs baseline: 4.3922x; 1.0030x over previous
#include <cuda_runtime.h>

#define NN 50000
#define NE 800000
#define HD 64
#define NL 4
#define AS_LD 68

// ---------------- device scratch ----------------
__device__ __align__(16) float g_h[2][(size_t)NN * HD];
__device__ __align__(16) float g_S[(size_t)NN * HD];        // segment-summed relu(pre1) per node
__device__ __align__(16) float g_uv[(size_t)NN * 128];      // u (cols 0-63), v (cols 64-127)
__device__ __align__(16) float g_deg[NN];
__device__ __align__(16) int   g_src[NE];
__device__ __align__(16) int   g_dst[NE];
__device__ __align__(16) float4 g_evec4[NE];
// CSR (sorted by dst)
__device__ __align__(16) int   g_cnt[NN];
__device__ __align__(16) int   g_fill[NN];
__device__ __align__(16) int   g_rowptr[NN + 1];
__device__ __align__(16) int   g_src_s[NE];
__device__ __align__(16) float4 g_evec_s[NE];
// folded weights
__device__ __align__(16) float g_wfold[NL][3 * 64];         // edge_enc_w @ W1_e
__device__ __align__(16) float g_b1eff[NL][64];             // b1 + eeb @ W1_e
__device__ __align__(16) float g_wuv[NL][64 * 128];         // [W1a | W1b]
__device__ __align__(16) float g_nwf[NL][128 * 64];         // [M1_top ; W2 @ M1_bot]
__device__ __align__(16) float g_q[NL][64];                 // b2 @ M1_bot

// ---------------- f32x2 packed-FMA helpers ----------------
__device__ __forceinline__ void ffma2(unsigned long long& d, unsigned long long a, unsigned long long b) {
    asm("fma.rn.f32x2 %0, %1, %2, %0;" : "+l"(d) : "l"(a), "l"(b));
}
__device__ __forceinline__ unsigned long long splat2(float x) {
    unsigned long long r; asm("mov.b64 %0, {%1, %1};" : "=l"(r) : "f"(x)); return r;
}
__device__ __forceinline__ float2 unpk(unsigned long long v) {
    float2 f; asm("mov.b64 {%0, %1}, %2;" : "=f"(f.x), "=f"(f.y) : "l"(v)); return f;
}

#define GEMM_STEP(ACC, APTR, BPTR) do {                                        \
    float4 a4_ = *reinterpret_cast<const float4*>(APTR);                        \
    ulonglong2 bb_ = *reinterpret_cast<const ulonglong2*>(BPTR);                \
    unsigned long long s_;                                                      \
    s_ = splat2(a4_.x); ffma2(ACC[0][0], s_, bb_.x); ffma2(ACC[0][1], s_, bb_.y); \
    s_ = splat2(a4_.y); ffma2(ACC[1][0], s_, bb_.x); ffma2(ACC[1][1], s_, bb_.y); \
    s_ = splat2(a4_.z); ffma2(ACC[2][0], s_, bb_.x); ffma2(ACC[2][1], s_, bb_.y); \
    s_ = splat2(a4_.w); ffma2(ACC[3][0], s_, bb_.x); ffma2(ACC[3][1], s_, bb_.y); \
} while (0)

#define GEMM_STEP2(ACU, ACV, APTR, BU, BV) do {                                \
    float4 a4_ = *reinterpret_cast<const float4*>(APTR);                        \
    ulonglong2 bu_ = *reinterpret_cast<const ulonglong2*>(BU);                  \
    ulonglong2 bv_ = *reinterpret_cast<const ulonglong2*>(BV);                  \
    unsigned long long s_;                                                      \
    s_ = splat2(a4_.x); ffma2(ACU[0][0], s_, bu_.x); ffma2(ACU[0][1], s_, bu_.y); ffma2(ACV[0][0], s_, bv_.x); ffma2(ACV[0][1], s_, bv_.y); \
    s_ = splat2(a4_.y); ffma2(ACU[1][0], s_, bu_.x); ffma2(ACU[1][1], s_, bu_.y); ffma2(ACV[1][0], s_, bv_.x); ffma2(ACV[1][1], s_, bv_.y); \
    s_ = splat2(a4_.z); ffma2(ACU[2][0], s_, bu_.x); ffma2(ACU[2][1], s_, bu_.y); ffma2(ACV[2][0], s_, bv_.x); ffma2(ACV[2][1], s_, bv_.y); \
    s_ = splat2(a4_.w); ffma2(ACU[3][0], s_, bu_.x); ffma2(ACU[3][1], s_, bu_.y); ffma2(ACV[3][0], s_, bv_.x); ffma2(ACV[3][1], s_, bv_.y); \
} while (0)

// ---------------- prep kernels ----------------
__global__ void zero_counters() {
    int i = blockIdx.x * 256 + threadIdx.x;
    if (i < NN) { g_deg[i] = 0.f; g_cnt[i] = 0; g_fill[i] = 0; }
}

__global__ void prep_edges(const int* __restrict__ ei, const float* __restrict__ pos) {
    int i = blockIdx.x * 256 + threadIdx.x;
    if (i >= NE) return;
    int s = min(max(ei[i], 0), NN - 1);
    int d = min(max(ei[NE + i], 0), NN - 1);
    g_src[i] = s;
    g_dst[i] = d;
    const float* ps = pos + 3 * (size_t)s;
    const float* pd = pos + 3 * (size_t)d;
    g_evec4[i] = make_float4(pd[0] - ps[0], pd[1] - ps[1], pd[2] - ps[2], 0.f);
    atomicAdd(&g_cnt[d], 1);
    atomicAdd(&g_deg[d], 1.f);
}

// single-block exclusive scan: g_rowptr[0..NN]
#define SCN_C 49   // ceil(50000/1024)
__global__ void scan_counts() {
    __shared__ int part[1024];
    int t = threadIdx.x;
    int base = t * SCN_C;
    int sum = 0;
    for (int i = 0; i < SCN_C; i++) {
        int idx = base + i;
        if (idx < NN) sum += g_cnt[idx];
    }
    part[t] = sum;
    __syncthreads();
    for (int off = 1; off < 1024; off <<= 1) {
        int v = (t >= off) ? part[t - off] : 0;
        __syncthreads();
        if (t >= off) part[t] += v;
        __syncthreads();
    }
    int run = (t > 0) ? part[t - 1] : 0;
    for (int i = 0; i < SCN_C; i++) {
        int idx = base + i;
        if (idx < NN) { g_rowptr[idx] = run; run += g_cnt[idx]; }
    }
    if (t == 1023) g_rowptr[NN] = run;
}

__global__ void fill_csr() {
    int i = blockIdx.x * 256 + threadIdx.x;
    if (i >= NE) return;
    int d = g_dst[i];
    int pos = g_rowptr[d] + atomicAdd(&g_fill[d], 1);
    g_src_s[pos] = g_src[i];
    g_evec_s[pos] = g_evec4[i];
}

// wfold[l][c][j] = sum_m eew[c][m] * ew1[l][(128+m)][j]
__global__ void prep_wfold(const float* __restrict__ ew1, const float* __restrict__ eew) {
    int idx = blockIdx.x * 192 + threadIdx.x;
    if (idx >= NL * 3 * 64) return;
    int j = idx & 63;
    int c = (idx >> 6) % 3;
    int l = idx / 192;
    const float* w = ew1 + (size_t)l * 192 * 64 + 128 * 64 + j;
    float v = 0.f;
    #pragma unroll 8
    for (int m = 0; m < 64; m++) v += eew[c * 64 + m] * w[(size_t)m * 64];
    g_wfold[l][c * 64 + j] = v;
}

__global__ void prep_b1eff(const float* __restrict__ ew1, const float* __restrict__ eeb,
                           const float* __restrict__ eb1) {
    int idx = blockIdx.x * 64 + threadIdx.x;
    if (idx >= NL * 64) return;
    int j = idx & 63;
    int l = idx >> 6;
    float v = eb1[l * 64 + j];
    const float* w = ew1 + (size_t)l * 192 * 64 + 128 * 64 + j;
    #pragma unroll 8
    for (int m = 0; m < 64; m++) v += eeb[m] * w[(size_t)m * 64];
    g_b1eff[l][j] = v;
}

__global__ void prep_wuv(const float* __restrict__ ew1) {
    int idx = blockIdx.x * 256 + threadIdx.x;
    if (idx >= NL * 64 * 128) return;
    int j = idx & 127;
    int k = (idx >> 7) & 63;
    int l = idx >> 13;
    const float* base = ew1 + (size_t)l * 192 * 64;
    g_wuv[l][k * 128 + j] = (j < 64) ? base[k * 64 + j] : base[(64 + k) * 64 + (j - 64)];
}

__global__ void prep_nwf(const float* __restrict__ nw1, const float* __restrict__ ew2) {
    int idx = blockIdx.x * 256 + threadIdx.x;
    if (idx >= NL * 128 * 64) return;
    int j = idx & 63;
    int k = (idx >> 6) & 127;
    int l = idx >> 13;
    const float* m1 = nw1 + (size_t)l * 128 * 64;
    float v;
    if (k < 64) {
        v = m1[k * 64 + j];
    } else {
        int p = k - 64;
        const float* w2 = ew2 + (size_t)l * 64 * 64 + p * 64;
        v = 0.f;
        #pragma unroll 8
        for (int m = 0; m < 64; m++) v += w2[m] * m1[(64 + m) * 64 + j];
    }
    g_nwf[l][k * 64 + j] = v;
}

__global__ void prep_q(const float* __restrict__ nw1, const float* __restrict__ eb2) {
    int idx = blockIdx.x * 64 + threadIdx.x;
    if (idx >= NL * 64) return;
    int j = idx & 63;
    int l = idx >> 6;
    const float* m1 = nw1 + (size_t)l * 128 * 64;
    float v = 0.f;
    #pragma unroll 8
    for (int m = 0; m < 64; m++) v += eb2[l * 64 + m] * m1[(64 + m) * 64 + j];
    g_q[l][j] = v;
}

__global__ void encoder(const float* __restrict__ nf, const float* __restrict__ w,
                        const float* __restrict__ b) {
    int idx = blockIdx.x * 256 + threadIdx.x;
    if (idx >= NN * HD) return;
    int j = idx & 63;
    int n = idx >> 6;
    float acc = b[j];
    acc += nf[n * 3 + 0] * w[j] + nf[n * 3 + 1] * w[64 + j] + nf[n * 3 + 2] * w[128 + j];
    g_h[0][idx] = acc;
}

// ---------------- uv kernel: uv[n] = h[n] @ [W1a|W1b] ----------------
static constexpr int UV_SMEM = (64 * AS_LD + 64 * 128) * 4;   // 50176
__global__ __launch_bounds__(256)
void uv_kernel(int l) {
    extern __shared__ float sm[];
    float* As = sm;
    float* Bs = sm + 64 * AS_LD;
    const float* hc = g_h[l & 1];
    int tid = threadIdx.x;
    int nbase = blockIdx.x * 64;

    {
        const float4* s = reinterpret_cast<const float4*>(g_wuv[l]);
        float4* d = reinterpret_cast<float4*>(Bs);
        for (int i = tid; i < 64 * 128 / 4; i += 256) d[i] = s[i];
    }
    {
        int n = tid & 63;
        int c0 = tid >> 6;
        int node = nbase + n;
        bool valid = node < NN;
        int ncl = valid ? node : (NN - 1);
        const float4* hp = reinterpret_cast<const float4*>(hc + (size_t)ncl * HD);
        float4 z = make_float4(0.f, 0.f, 0.f, 0.f);
        #pragma unroll
        for (int c = c0; c < 16; c += 4) {
            float4 v = valid ? hp[c] : z;
            As[(4 * c + 0) * AS_LD + n] = v.x;
            As[(4 * c + 1) * AS_LD + n] = v.y;
            As[(4 * c + 2) * AS_LD + n] = v.z;
            As[(4 * c + 3) * AS_LD + n] = v.w;
        }
    }
    __syncthreads();

    int tx4 = (tid & 15) * 4;
    int ty4 = (tid >> 4) * 4;
    unsigned long long acu[4][2] = {}, acv[4][2] = {};
    #pragma unroll 4
    for (int k = 0; k < 64; ++k)
        GEMM_STEP2(acu, acv, As + k * AS_LD + tx4, Bs + k * 128 + ty4, Bs + k * 128 + 64 + ty4);

    #pragma unroll
    for (int i = 0; i < 4; i++) {
        int node = nbase + tx4 + i;
        if (node < NN) {
            float2 u0 = unpk(acu[i][0]), u1 = unpk(acu[i][1]);
            float2 v0 = unpk(acv[i][0]), v1 = unpk(acv[i][1]);
            *reinterpret_cast<float4*>(g_uv + (size_t)node * 128 + ty4)      = make_float4(u0.x, u0.y, u1.x, u1.y);
            *reinterpret_cast<float4*>(g_uv + (size_t)node * 128 + 64 + ty4) = make_float4(v0.x, v0.y, v1.x, v1.y);
        }
    }
}

// ---------------- edge gather (CSR segment sum): S[w] = sum_e relu(u[src]+v[w]+ev@wf+b) ----------------
// one warp per dst node, 2 columns per lane, plain store (no atomics)
__global__ __launch_bounds__(256)
void edge_gather(int l) {
    int g = blockIdx.x * 256 + threadIdx.x;
    int w = g >> 5;
    int lane = g & 31;
    if (w >= NN) return;
    int c2 = lane * 2;

    const float* wf = g_wfold[l];
    float2 w0 = *reinterpret_cast<const float2*>(wf + c2);
    float2 w1 = *reinterpret_cast<const float2*>(wf + 64 + c2);
    float2 w2 = *reinterpret_cast<const float2*>(wf + 128 + c2);
    float2 b  = *reinterpret_cast<const float2*>(g_b1eff[l] + c2);
    float2 vv = *reinterpret_cast<const float2*>(g_uv + (size_t)w * 128 + 64 + c2);
    float bx = vv.x + b.x, by = vv.y + b.y;

    int beg = g_rowptr[w];
    int end = g_rowptr[w + 1];
    float ax = 0.f, ay = 0.f;

    // software pipeline: prefetch src/evec/u one iteration ahead
    float4 ev_c;
    float2 uu_c;
    if (beg < end) {
        int s0 = g_src_s[beg];
        ev_c = g_evec_s[beg];
        uu_c = *reinterpret_cast<const float2*>(g_uv + (size_t)s0 * 128 + c2);
    }
    for (int i = beg; i < end; i++) {
        float4 ev = ev_c;
        float2 uu = uu_c;
        if (i + 1 < end) {
            int sn = g_src_s[i + 1];
            ev_c = g_evec_s[i + 1];
            uu_c = *reinterpret_cast<const float2*>(g_uv + (size_t)sn * 128 + c2);
        }
        float p0 = fmaf(ev.x, w0.x, fmaf(ev.y, w1.x, fmaf(ev.z, w2.x, uu.x + bx)));
        float p1 = fmaf(ev.x, w0.y, fmaf(ev.y, w1.y, fmaf(ev.z, w2.y, uu.y + by)));
        ax += fmaxf(p0, 0.f);
        ay += fmaxf(p1, 0.f);
    }
    *reinterpret_cast<float2*>(g_S + (size_t)w * HD + c2) = make_float2(ax, ay);
}

// ---------------- node MLP (fused agg) ----------------
static constexpr int NODE_SMEM = (128 * AS_LD + 128 * 64 + 64 * 64 + 64 + 64) * 4;  // 84480
__global__ __launch_bounds__(256, 2)
void node_kernel(const float* __restrict__ nb1, const float* __restrict__ nw2,
                 const float* __restrict__ nb2, int l) {
    extern __shared__ float sm[];
    float* As  = sm;
    float* W1s = sm + 128 * AS_LD;
    float* W2s = W1s + 128 * 64;
    float* qs  = W2s + 64 * 64;
    float* Dg  = qs + 64;

    const float* hc = g_h[l & 1];
    float* hn = g_h[(l + 1) & 1];
    int tid = threadIdx.x;
    int nbase = blockIdx.x * 64;

    {
        const float4* s1 = reinterpret_cast<const float4*>(g_nwf[l]);
        float4* d1 = reinterpret_cast<float4*>(W1s);
        for (int i = tid; i < 128 * 64 / 4; i += 256) d1[i] = s1[i];
        const float4* s2 = reinterpret_cast<const float4*>(nw2 + (size_t)l * 64 * 64);
        float4* d2 = reinterpret_cast<float4*>(W2s);
        for (int i = tid; i < 64 * 64 / 4; i += 256) d2[i] = s2[i];
        if (tid < 64) {
            qs[tid] = g_q[l][tid];
            int node = nbase + tid;
            Dg[tid] = (node < NN) ? g_deg[node] : 0.f;
        }
    }

    {
        int n = tid & 63;
        int c0 = tid >> 6;
        int node = nbase + n;
        bool valid = node < NN;
        int ncl = valid ? node : (NN - 1);
        const float4* hp = reinterpret_cast<const float4*>(hc + (size_t)ncl * HD);
        const float4* ap = reinterpret_cast<const float4*>(g_S + (size_t)ncl * HD);
        float4 z = make_float4(0.f, 0.f, 0.f, 0.f);
        #pragma unroll
        for (int c = c0; c < 16; c += 4) {
            float4 v = valid ? hp[c] : z;
            As[(4 * c + 0) * AS_LD + n] = v.x;
            As[(4 * c + 1) * AS_LD + n] = v.y;
            As[(4 * c + 2) * AS_LD + n] = v.z;
            As[(4 * c + 3) * AS_LD + n] = v.w;
            float4 w = valid ? ap[c] : z;
            As[(64 + 4 * c + 0) * AS_LD + n] = w.x;
            As[(64 + 4 * c + 1) * AS_LD + n] = w.y;
            As[(64 + 4 * c + 2) * AS_LD + n] = w.z;
            As[(64 + 4 * c + 3) * AS_LD + n] = w.w;
        }
    }
    __syncthreads();

    int tx4 = (tid & 15) * 4;
    int ty4 = (tid >> 4) * 4;

    unsigned long long acc[4][2] = {};
    #pragma unroll 4
    for (int k = 0; k < 128; ++k)
        GEMM_STEP(acc, As + k * AS_LD + tx4, W1s + k * 64 + ty4);

    float hid[4][4];
    {
        float2 bA = *reinterpret_cast<const float2*>(nb1 + (size_t)l * 64 + ty4);
        float2 bB = *reinterpret_cast<const float2*>(nb1 + (size_t)l * 64 + ty4 + 2);
        float2 qA = *reinterpret_cast<const float2*>(qs + ty4);
        float2 qB = *reinterpret_cast<const float2*>(qs + ty4 + 2);
        #pragma unroll
        for (int i = 0; i < 4; i++) {
            float dg = Dg[tx4 + i];
            float2 u = unpk(acc[i][0]);
            float2 v = unpk(acc[i][1]);
            hid[i][0] = fmaxf(fmaf(dg, qA.x, u.x + bA.x), 0.f);
            hid[i][1] = fmaxf(fmaf(dg, qA.y, u.y + bA.y), 0.f);
            hid[i][2] = fmaxf(fmaf(dg, qB.x, v.x + bB.x), 0.f);
            hid[i][3] = fmaxf(fmaf(dg, qB.y, v.y + bB.y), 0.f);
        }
    }
    __syncthreads();
    float* Hs = As;
    #pragma unroll
    for (int j = 0; j < 4; j++)
        *reinterpret_cast<float4*>(Hs + (ty4 + j) * AS_LD + tx4) =
            make_float4(hid[0][j], hid[1][j], hid[2][j], hid[3][j]);
    __syncthreads();

    unsigned long long acc2[4][2] = {};
    #pragma unroll 4
    for (int k = 0; k < 64; ++k)
        GEMM_STEP(acc2, Hs + k * AS_LD + tx4, W2s + k * 64 + ty4);

    float2 bA = *reinterpret_cast<const float2*>(nb2 + (size_t)l * 64 + ty4);
    float2 bB = *reinterpret_cast<const float2*>(nb2 + (size_t)l * 64 + ty4 + 2);
    #pragma unroll
    for (int i = 0; i < 4; i++) {
        int node = nbase + tx4 + i;
        if (node < NN) {
            float2 u = unpk(acc2[i][0]);
            float2 v = unpk(acc2[i][1]);
            *reinterpret_cast<float4*>(hn + (size_t)node * HD + ty4) =
                make_float4(u.x + bA.x, u.y + bA.y, v.x + bB.x, v.y + bB.y);
        }
    }
}

// ---------------- decoder ----------------
__global__ void decoder(const float* __restrict__ dw, const float* __restrict__ db,
                        float* __restrict__ out) {
    int gid = blockIdx.x * 256 + threadIdx.x;
    int w = gid >> 5, lane = gid & 31;
    if (w >= NN) return;
    const float* hr = g_h[0] + (size_t)w * HD;
    float v = hr[lane] * dw[lane] + hr[lane + 32] * dw[lane + 32];
    #pragma unroll
    for (int o = 16; o > 0; o >>= 1) v += __shfl_down_sync(0xffffffffu, v, o);
    if (lane == 0) out[w] = v + db[0];
}

// ---------------- launch ----------------
#define NTILES ((NN + 63) / 64)   // 782

extern "C" void kernel_launch(void* const* d_in, const int* in_sizes, int n_in,
                              void* d_out, int out_size) {
    const float* node_pos  = (const float*)d_in[0];
    const float* node_feat = (const float*)d_in[1];
    const int*   eidx      = (const int*)d_in[2];
    const float* enc_w = (const float*)d_in[3];
    const float* enc_b = (const float*)d_in[4];
    const float* eew   = (const float*)d_in[5];
    const float* eeb   = (const float*)d_in[6];
    const float* ew1   = (const float*)d_in[7];
    const float* eb1   = (const float*)d_in[8];
    const float* ew2   = (const float*)d_in[9];
    const float* eb2   = (const float*)d_in[10];
    const float* nw1   = (const float*)d_in[11];
    const float* nb1   = (const float*)d_in[12];
    const float* nw2   = (const float*)d_in[13];
    const float* nb2   = (const float*)d_in[14];
    const float* dec_w = (const float*)d_in[15];
    const float* dec_b = (const float*)d_in[16];
    float* out = (float*)d_out;

    cudaFuncSetAttribute(uv_kernel, cudaFuncAttributeMaxDynamicSharedMemorySize, UV_SMEM);
    cudaFuncSetAttribute(node_kernel, cudaFuncAttributeMaxDynamicSharedMemorySize, NODE_SMEM);

    zero_counters<<<(NN + 255) / 256, 256>>>();
    prep_edges<<<(NE + 255) / 256, 256>>>(eidx, node_pos);
    scan_counts<<<1, 1024>>>();
    fill_csr<<<(NE + 255) / 256, 256>>>();
    prep_wfold<<<NL, 192>>>(ew1, eew);
    prep_b1eff<<<NL, 64>>>(ew1, eeb, eb1);
    prep_wuv<<<(NL * 64 * 128 + 255) / 256, 256>>>(ew1);
    prep_nwf<<<(NL * 128 * 64 + 255) / 256, 256>>>(nw1, ew2);
    prep_q<<<NL, 64>>>(nw1, eb2);
    encoder<<<(NN * HD + 255) / 256, 256>>>(node_feat, enc_w, enc_b);

    for (int l = 0; l < NL; ++l) {
        uv_kernel<<<NTILES, 256, UV_SMEM>>>(l);
        edge_gather<<<(NN * 32 + 255) / 256, 256>>>(l);
        node_kernel<<<NTILES, 256, NODE_SMEM>>>(nb1, nw2, nb2, l);
    }

    decoder<<<(NN * 32 + 255) / 256, 256>>>(dec_w, dec_b, out);
}